// round 17
// baseline (speedup 1.0000x reference)
#include <cuda_runtime.h>
#include <cstddef>
#include <cstdint>

// CTC loss forward. B=32, T=800, C=5000, L=100, S=201.
//
// R16: instruction-count attack. R11/R14/R15 (three different exchange
// structures) all ran 82-85us alpha; issue% shows ~41 instr/step at ~4.3cyc
// each -- with 1 warp/SMSP the kernel is INSTRUCTION-LATENCY-bound, so the
// lever is fewer instructions, not cheaper exchanges. Changes:
//  * plain log2-domain alpha, ONE float per state (no base+sum, no renorm,
//    no folds): even state = single-ex2 logaddexp; odd = 3-term parallel.
//  * exchange = 1 shfl float/step; publish float2 at window boundaries.
//  * running emission pointers + literal offsets inside the fully unrolled
//    6-step window; emit array padded so refills need no clamps.
//  * gather (36us DRAM floor) + fused last-block reduction unchanged.

#define Bb 32
#define Tt 800
#define Cc 5000
#define Ll 100
#define EP 128            // emit row stride (floats), line-aligned
#define NEGV (-1e30f)
#define LOG2E 1.4426950408889634f
#define LN2   0.6931471805599453f
#define W 6               // window length == halo depth == ring depth
#define NTHR 128

// Padded by 16 rows: window refills prefetch up to ~last+2W rows ahead.
__device__ float    g_emit[((size_t)Bb * Tt + 16) * EP];
__device__ float    g_tot[Bb];
__device__ unsigned g_done;          // self-resetting

__device__ __forceinline__ float ex2f(float x) {
    float y; asm("ex2.approx.ftz.f32 %0, %1;" : "=f"(y) : "f"(x)); return y;
}
__device__ __forceinline__ float lg2f(float x) {
    float y; asm("lg2.approx.ftz.f32 %0, %1;" : "=f"(y) : "f"(x)); return y;
}

// One CTC time step, plain log2 domain. ae = even-state alpha, ao = odd.
// Neighbor's odd alpha via shfl; lane 0 self-clamps (halo contains it).
#define STEP(eb_, eo_)                                                     \
    {                                                                      \
        float nb = __shfl_up_sync(0xffffffffu, ao, 1);                     \
        /* even (blank): preds ae, nb -- single-ex2 logaddexp */           \
        float d0 = __fadd_rn(ae, -nb);                                     \
        float u0 = ex2f(fminf(d0, -d0));                                   \
        float m0 = fmaxf(ae, nb);                                          \
        float ne = __fadd_rn(__fadd_rn(m0, lg2f(__fadd_rn(1.f, u0))),      \
                             (eb_));                                       \
        /* odd: preds ao, ae, (skip? nb : NEG) -- 3-term parallel */       \
        float bz = skip ? nb : NEGV;                                       \
        float m1 = fmaxf(ao, fmaxf(ae, bz));                               \
        float s1 = __fadd_rn(__fadd_rn(ex2f(__fadd_rn(ao, -m1)),           \
                                       ex2f(__fadd_rn(ae, -m1))),          \
                             ex2f(__fadd_rn(bz, -m1)));                    \
        float no = __fadd_rn(__fadd_rn(m1, lg2f(s1)), (eo_));              \
        ae = ne; ao = no;                                                  \
    }

// ---------------------------------------------------------------------------
// Kernel 1: gather (full chip). emit[bt][j] = LOG2E * lp[bt, col(j)].
// ---------------------------------------------------------------------------
__global__ void gather_kernel(const float* __restrict__ lp,
                              const int* __restrict__ targets,
                              const int* __restrict__ ilen) {
    int idx = blockIdx.x * blockDim.x + threadIdx.x;
    const int total = Bb * Tt * (Ll + 1);
    if (idx >= total) return;
    int j  = idx % (Ll + 1);
    int bt = idx / (Ll + 1);
    int b  = bt / Tt;
    int t  = bt - b * Tt;
    if (t >= ilen[b]) return;
    int c = (j == 0) ? 0 : targets[b * Ll + (j - 1)];
    g_emit[(size_t)bt * EP + j] = LOG2E * __ldg(lp + (size_t)bt * Cc + c);
}

// ---------------------------------------------------------------------------
// Kernel 2: shfl-windowed plain-log alpha + fused reduction. grid=B, 128thr.
// ---------------------------------------------------------------------------
__global__ __launch_bounds__(NTHR, 1)
void ctc_alpha(const int* __restrict__ targets,
               const int* __restrict__ ilen,
               const int* __restrict__ tlen,
               float* __restrict__ out)
{
    // pub[buf][slot+6] = (ae, ao); indices 0..5 = permanent left pads.
    __shared__ float2 pub[2][110];
    __shared__ int s_lastflag;

    const int b = blockIdx.x;
    const int i = threadIdx.x;
    const int w = i >> 5;
    const int l = i & 31;
    const int slot = 26 * w - 6 + l;     // -6 .. 103
    const int last = ilen[b] - 1;        // >= 599 for this problem

    const int tgR  = (slot >= 0 && slot < Ll)  ? targets[b * Ll + slot]     : 0;
    const int tgpR = (slot >= 1 && slot <= Ll) ? targets[b * Ll + slot - 1] : -1;
    const bool skip = (tgR != tgpR);
    const int jo = (slot >= 0 && slot < Ll) ? slot + 1 : 0;  // odd emission col

    const float* __restrict__ em = g_emit + (size_t)b * Tt * EP;

    if (i < W) {                         // left pads, both buffers, once
        pub[0][i] = make_float2(NEGV, NEGV);
        pub[1][i] = make_float2(NEGV, NEGV);
    }

    // t=0 init: only slot 0 live (states 0 and 1).
    float ae = (slot == 0) ? em[0]  : NEGV;
    float ao = (slot == 0) ? em[jo] : NEGV;

    __syncthreads();                     // pads visible before first reload

    // Prefetch ring for window 0 (steps 1..6); last >= 599 so no clamps.
    float eb[W], eo[W];
    {
        const float* p0 = em + EP;       // step t=1 row
        const float* p1 = p0 + jo;
#pragma unroll
        for (int u = 0; u < W; ++u) {
            eb[u] = p0[u * EP];
            eo[u] = p1[u * EP];
        }
    }

    // Running pointers for refills (always one window ahead).
    const float* pe  = em + (size_t)(W + 1) * EP;   // blank col, next window
    const float* peo = pe + jo;                     // own odd col

    const int nwin = last / W;           // full windows (steps 1..nwin*W)
    int buf = 0;

    for (int n = 0; n < nwin; ++n) {
#pragma unroll
        for (int u = 0; u < W; ++u) {    // u literal -> rings in registers
            const float ebv = eb[u], eov = eo[u];
            eb[u] = pe[u * EP];          // refill for next window; may read
            eo[u] = peo[u * EP];         // padded/garbage rows (never used)
            STEP(ebv, eov);
        }
        pe  += (size_t)W * EP;
        peo += (size_t)W * EP;
        // Window boundary: publish output lanes, reload halo lanes.
        buf ^= 1;
        if (l >= W) pub[buf][slot + 6] = make_float2(ae, ao);
        __syncthreads();
        if (l < W) {
            float2 v = pub[buf][slot + 6];
            ae = v.x; ao = v.y;
        }
    }

    // Remainder steps (<= 5): direct loads; contamination <= 5 < halo 6.
    for (int t = nwin * W + 1; t <= last; ++t) {
        const float ebv = em[(size_t)t * EP];
        const float eov = em[(size_t)t * EP + jo];
        STEP(ebv, eov);
    }

    // Publish final output lanes.
    buf ^= 1;
    if (l >= W) pub[buf][slot + 6] = make_float2(ae, ao);
    __syncthreads();

    if (i == 0) {
        int Lb = tlen[b];
        float x = pub[buf][Lb + 6].x;        // even state 2Lb   (slot Lb)
        float y = pub[buf][Lb - 1 + 6].y;    // odd  state 2Lb-1 (slot Lb-1)
        float m = fmaxf(x, y);
        g_tot[b] = LN2 * (m + lg2f(ex2f(x - m) + ex2f(y - m)));
        __threadfence();
        unsigned v = atomicAdd(&g_done, 1u);
        s_lastflag = (v == Bb - 1u) ? 1 : 0;
    }
    __syncthreads();

    if (s_lastflag && i < 32) {              // last block: fused reduction
        __threadfence();
        float tot = g_tot[i];
        float il  = (float)ilen[i];
        bool  ok  = tot > NEGV * 0.5f;
        float tsum = ok ? tot : 0.f;
        float tf   = ok ? il  : 0.f;
        float af   = il;
#pragma unroll
        for (int s = 16; s >= 1; s >>= 1) {
            tsum += __shfl_down_sync(0xFFFFFFFFu, tsum, s);
            tf   += __shfl_down_sync(0xFFFFFFFFu, tf, s);
            af   += __shfl_down_sync(0xFFFFFFFFu, af, s);
        }
        if (i == 0) {
            out[0] = tsum; out[1] = tf; out[2] = af;
            g_done = 0;                      // reset for next graph replay
        }
    }
}

// ---------------------------------------------------------------------------
extern "C" void kernel_launch(void* const* d_in, const int* in_sizes, int n_in,
                              void* d_out, int out_size) {
    const float* lp      = (const float*)d_in[0];  // nnet_output [B,T,C] f32
    const int*   targets = (const int*)  d_in[1];  // [B,L] i32
    const int*   ilen    = (const int*)  d_in[2];  // [B] i32
    const int*   tlen    = (const int*)  d_in[3];  // [B] i32

    const int total = Bb * Tt * (Ll + 1);
    gather_kernel<<<(total + 255) / 256, 256>>>(lp, targets, ilen);
    ctc_alpha<<<Bb, NTHR>>>(targets, ilen, tlen, (float*)d_out);
}